// round 16
// baseline (speedup 1.0000x reference)
#include <cuda_runtime.h>
#include <cuda_bf16.h>

#define NB 64
#define NT 512
#define EMBED 1024
#define WIN 64
#define NK (2*WIN+1)   // 129
#define GW 256         // matrix W dimension
#define NPROD 32       // producer blocks in phase C
#define NKMAX 5        // keys per producer slot (block 31 uses all 5)

// Scratch (device globals: no allocation allowed)
__device__ float g_w[EMBED];             // REDG accumulation target (zeroed post-use)
__device__ float g_ypart[NPROD][EMBED];
__device__ float g_zpart[NPROD];
__device__ float g_o[EMBED];
// Grid barrier: EXACT style that has passed 7/9 (atomic arrive + atomic poll + nanosleep).
__device__ unsigned g_arrive = 0;
__device__ unsigned g_rel = 0;

__device__ __forceinline__ void grid_sync() {
    __threadfence();
    __syncthreads();
    if (threadIdx.x == 0) {
        unsigned a = atomicAdd(&g_arrive, 1u) + 1u;
        unsigned target = (a + NB - 1u) / NB;
        if ((a % NB) == 0u) {
            atomicAdd(&g_rel, 1u);
        } else {
            while (atomicAdd(&g_rel, 0u) < target) { __nanosleep(32); }
        }
    }
    __syncthreads();
}

__device__ __forceinline__ float warp_reduce(float v) {
    #pragma unroll
    for (int o = 16; o; o >>= 1) v += __shfl_xor_sync(0xffffffffu, v, o);
    return v;
}

__device__ __forceinline__ float dot4(float4 a, float4 b) {
    return a.x * b.x + a.y * b.y + a.z * b.z + a.w * b.w;
}

__device__ __forceinline__ void cp_async16(unsigned smem_addr, const void* gptr) {
    asm volatile("cp.async.cg.shared.global [%0], [%1], 16;"
                 :: "r"(smem_addr), "l"(gptr));
}

__device__ __forceinline__ void redg_add(float* gptr, float v) {
    asm volatile("red.global.add.f32 [%0], %1;" :: "l"(gptr), "f"(v) : "memory");
}

// Dynamic smem layout (floats):
//  xs    [0,1024)       x / abar / o staging (256 float4)
//  R1    [1024,2048)    w-partial combine (256 float4)
//  misc  [2048,2080)    q broadcast (16) / warp accs / zinv / p_k
//  dotp  [2080,2208)    16 warps x 8 slots
//  keyS  [4000,9120)    5 keys x 1024 (producers)
//  WvS   [9120,25504)   16 Wv rows (64KB)
//  WoS   [25504,41888)  16 Wo rows (64KB)
#define SM_FLOATS 41888
#define SM_BYTES  (SM_FLOATS * 4)

__global__ void __launch_bounds__(NT, 1)
fused_local_attn(const float* __restrict__ matrix,
                 const float* __restrict__ Wq, const float* __restrict__ bq,
                 const float* __restrict__ Wk,
                 const float* __restrict__ Wv, const float* __restrict__ bv,
                 const float* __restrict__ Wo, const float* __restrict__ bo,
                 const int* __restrict__ ppx, const int* __restrict__ ppy,
                 float* __restrict__ out)
{
    const int tid  = threadIdx.x;
    const int bid  = blockIdx.x;
    const int wid  = tid >> 5;
    const int lane = tid & 31;

    extern __shared__ __align__(16) float sm[];
    float4* xs_4   = (float4*)sm;
    float4* R1_4   = (float4*)(sm + 1024);
    float*  misc   = sm + 2048;
    float*  dotp   = sm + 2080;
    float4* keyS_4 = (float4*)(sm + 4000);
    float4* WvS_4  = (float4*)(sm + 9120);
    float4* WoS_4  = (float4*)(sm + 25504);

    // ---- Top-of-kernel prefetches ---------------------------------------
    {
        unsigned wv_s = (unsigned)__cvta_generic_to_shared(WvS_4);
        unsigned wo_s = (unsigned)__cvta_generic_to_shared(WoS_4);
        const float4* vsrc = (const float4*)Wv + (size_t)bid * 4096;
        const float4* osrc = (const float4*)Wo + (size_t)bid * 4096;
        #pragma unroll
        for (int j = 0; j < 8; j++)
            cp_async16(wv_s + (unsigned)(tid + j * 512) * 16u, vsrc + tid + j * 512);
        asm volatile("cp.async.commit_group;");
        #pragma unroll
        for (int j = 0; j < 8; j++)
            cp_async16(wo_s + (unsigned)(tid + j * 512) * 16u, osrc + tid + j * 512);
        asm volatile("cp.async.commit_group;");
    }

    // Biases: my_bq lives in LANE 0 of warp `wid` (the thread that writes
    // misc[wid] in phase AB). my_bv/my_bo live in tid<16 (their consumers).
    float my_bq = 0.f, my_bv = 0.f, my_bo = 0.f;
    if (lane == 0) my_bq = __ldcg(&bq[bid * 16 + wid]);
    if (tid < 16) {
        my_bv = __ldcg(&bv[bid * 16 + tid]);
        my_bo = __ldcg(&bo[bid * 16 + tid]);
    }

    const int px = __ldcg(&ppx[0]), py = __ldcg(&ppy[0]);
    const float* rowbase = matrix + (size_t)(2 * px - WIN) * GW * EMBED;
    const float4* xvec4 = (const float4*)(rowbase + (size_t)(2 * py - WIN) * EMBED);
    const float4* keys4 = (const float4*)(rowbase + (size_t)(py - WIN) * EMBED);

    if (bid < NPROD) {
        unsigned k_s = (unsigned)__cvta_generic_to_shared(keyS_4);
        const float4* ksrc = keys4 + (size_t)(bid * 4) * 256;   // 5 keys = 1280 f4
        #pragma unroll
        for (int j = 0; j < 3; j++) {
            int idx = tid + j * 512;
            if (idx < NKMAX * 256)
                cp_async16(k_s + (unsigned)idx * 16u, ksrc + idx);
        }
        asm volatile("cp.async.commit_group;");
    }

    // ===== Phase AB: q rows -> local Wk partial -> REDG into g_w =========
    {
        if (tid < 256) xs_4[tid] = xvec4[tid];
        __syncthreads();
        // q for this block's 16 rows (1 warp/row)
        int row = bid * 16 + wid;
        const float4* Wrow = (const float4*)(Wq + (size_t)row * EMBED);
        float acc = 0.f;
        #pragma unroll
        for (int i = 0; i < 8; i++)
            acc += dot4(Wrow[i * 32 + lane], xs_4[i * 32 + lane]);
        acc = warp_reduce(acc);
        if (lane == 0) misc[wid] = acc + my_bq;   // q_f with bias (lane0 holds bq[row])
        __syncthreads();
        // partial w: group g = tid>>8 covers f = g*8..g*8+7; ei = tid&255 spans e
        const int grp = tid >> 8;
        const int ei  = tid & 255;
        float4 facc = make_float4(0.f, 0.f, 0.f, 0.f);
        #pragma unroll
        for (int j = 0; j < 8; j++) {
            int f = grp * 8 + j;
            float qf = misc[f];
            float4 kw = ((const float4*)Wk)[(size_t)(bid * 16 + f) * 256 + ei];
            facc.x += qf * kw.x; facc.y += qf * kw.y;
            facc.z += qf * kw.z; facc.w += qf * kw.w;
        }
        if (grp == 0) R1_4[ei] = facc;
        __syncthreads();
        if (grp == 1) {
            float4 t4 = R1_4[ei];
            t4.x += facc.x; t4.y += facc.y; t4.z += facc.z; t4.w += facc.w;
            float* dst = &g_w[ei * 4];
            redg_add(dst + 0, t4.x);
            redg_add(dst + 1, t4.y);
            redg_add(dst + 2, t4.z);
            redg_add(dst + 3, t4.w);
        }
    }
    grid_sync();   // #1  (threadfence orders the REDG adds)

    // ===== Phase C (producers): w read (L2-hot), s_k, p_k, y, z ==========
    if (bid < NPROD) {
        asm volatile("cp.async.wait_group 0;");   // keys (and Wv/Wo) resident
        __syncthreads();
        const int nk = (bid == NPROD - 1) ? 5 : 4;
        float4 w4 = make_float4(0.f, 0.f, 0.f, 0.f);
        float4 kv[NKMAX];
        #pragma unroll
        for (int j = 0; j < NKMAX; j++) kv[j] = make_float4(0.f, 0.f, 0.f, 0.f);
        if (tid < 256) {
            w4 = __ldcg(&((const float4*)g_w)[tid]);
            #pragma unroll
            for (int j = 0; j < NKMAX; j++)
                kv[j] = keyS_4[j * 256 + tid];
        }
        #pragma unroll
        for (int j = 0; j < NKMAX; j++) {
            float p = (j < nk) ? dot4(w4, kv[j]) : 0.f;
            p = warp_reduce(p);
            if (lane == 0) dotp[wid * 8 + j] = p;
        }
        __syncthreads();
        if (tid < NKMAX) {
            float s = 0.f;
            #pragma unroll
            for (int w = 0; w < 8; w++) s += dotp[w * 8 + tid];   // warps 0-7 hold tid<256
            misc[20 + tid] = (tid < nk) ? __expf(s * 0.03125f) : 0.f;
        }
        __syncthreads();
        if (tid < 256) {
            float4 y = make_float4(0.f, 0.f, 0.f, 0.f);
            #pragma unroll
            for (int j = 0; j < NKMAX; j++) {
                float pk = misc[20 + j];
                y.x += pk * kv[j].x; y.y += pk * kv[j].y;
                y.z += pk * kv[j].z; y.w += pk * kv[j].w;
            }
            ((float4*)g_ypart[bid])[tid] = y;
        }
        if (tid == 0) {
            float z = 0.f;
            #pragma unroll
            for (int j = 0; j < NKMAX; j++) z += misc[20 + j];
            g_zpart[bid] = z;
        }
    }
    grid_sync();   // #2

    // ---- Block 33 (no other phase-E-exclusive work): zero g_w for next call --
    if (bid == 33 && tid < 256) {
        ((float4*)g_w)[tid] = make_float4(0.f, 0.f, 0.f, 0.f);
    }

    // ===== Phase E: abar from y/z parts, o = Wv @ abar + bv (smem Wv) ====
    asm volatile("cp.async.wait_group 0;");
    __syncthreads();
    {
        if (wid == 0) {
            float z = __ldcg(&g_zpart[lane]);     // 32 values
            z = warp_reduce(z);
            if (lane == 0) misc[16] = 1.f / z;
        }
        float4 s0 = make_float4(0.f, 0.f, 0.f, 0.f);
        float4 s1 = make_float4(0.f, 0.f, 0.f, 0.f);
        if (tid < 256) {
            #pragma unroll
            for (int p = 0; p < NPROD; p += 2) {
                float4 a0 = __ldcg(&((const float4*)g_ypart[p])[tid]);
                float4 a1 = __ldcg(&((const float4*)g_ypart[p + 1])[tid]);
                s0.x += a0.x; s0.y += a0.y; s0.z += a0.z; s0.w += a0.w;
                s1.x += a1.x; s1.y += a1.y; s1.z += a1.z; s1.w += a1.w;
            }
        }
        __syncthreads();                           // zinv ready
        if (tid < 256) {
            float zinv = misc[16];
            float4 ab;
            ab.x = (s0.x + s1.x) * zinv; ab.y = (s0.y + s1.y) * zinv;
            ab.z = (s0.z + s1.z) * zinv; ab.w = (s0.w + s1.w) * zinv;
            xs_4[tid] = ab;
        }
        __syncthreads();
        float acc = 0.f;
        #pragma unroll
        for (int i = 0; i < 8; i++)
            acc += dot4(WvS_4[wid * 256 + i * 32 + lane], xs_4[i * 32 + lane]);
        acc = warp_reduce(acc);
        if (lane == 0) misc[wid] = acc;
        __syncthreads();
        if (tid < 16) g_o[bid * 16 + tid] = misc[tid] + my_bv;
    }
    grid_sync();   // #3

    // ===== Phase F: out = Wo @ o + bo (smem Wo) ==========================
    {
        if (tid < 256) xs_4[tid] = __ldcg(&((const float4*)g_o)[tid]);
        __syncthreads();
        float acc = 0.f;
        #pragma unroll
        for (int i = 0; i < 8; i++)
            acc += dot4(WoS_4[wid * 256 + i * 32 + lane], xs_4[i * 32 + lane]);
        acc = warp_reduce(acc);
        if (lane == 0) misc[wid] = acc;
        __syncthreads();
        if (tid < 16) out[bid * 16 + tid] = misc[tid] + my_bo;
    }
}

extern "C" void kernel_launch(void* const* d_in, const int* in_sizes, int n_in,
                              void* d_out, int out_size) {
    const float* matrix = (const float*)d_in[0];
    const float* Wq = (const float*)d_in[1];
    const float* bq = (const float*)d_in[2];
    const float* Wk = (const float*)d_in[3];
    // d_in[4] = bk: eliminated (cancels in softmax ratio)
    const float* Wv = (const float*)d_in[5];
    const float* bv = (const float*)d_in[6];
    const float* Wo = (const float*)d_in[7];
    const float* bo = (const float*)d_in[8];
    const int* px = (const int*)d_in[9];
    const int* py = (const int*)d_in[10];

    cudaFuncSetAttribute(fused_local_attn,
                         cudaFuncAttributeMaxDynamicSharedMemorySize, SM_BYTES);
    fused_local_attn<<<NB, NT, SM_BYTES>>>(matrix, Wq, bq, Wk, Wv, bv, Wo, bo,
                                           px, py, (float*)d_out);
}

// round 17
// speedup vs baseline: 1.0347x; 1.0347x over previous
#include <cuda_runtime.h>
#include <cuda_bf16.h>

#define NB 128
#define NT 512
#define EMBED 1024
#define WIN 64
#define NK (2*WIN+1)   // 129
#define GW 256         // matrix W dimension
#define NPROD 32       // producer blocks in phase C
#define NKMAX 5        // keys per producer slot (block 31 uses all 5)

// Scratch (device globals: no allocation allowed)
__device__ float g_q[EMBED];
__device__ float g_wpart[4][EMBED];
__device__ float g_ypart[NPROD][EMBED];
__device__ float g_zpart[NPROD];
__device__ float g_o[EMBED];
// Grid barrier: EXACT style that has passed 8/10 (atomic arrive + atomic poll + nanosleep).
__device__ unsigned g_arrive = 0;
__device__ unsigned g_rel = 0;

__device__ __forceinline__ void grid_sync() {
    __threadfence();
    __syncthreads();
    if (threadIdx.x == 0) {
        unsigned a = atomicAdd(&g_arrive, 1u) + 1u;
        unsigned target = (a + NB - 1u) / NB;
        if ((a % NB) == 0u) {
            atomicAdd(&g_rel, 1u);
        } else {
            while (atomicAdd(&g_rel, 0u) < target) { __nanosleep(32); }
        }
    }
    __syncthreads();
}

__device__ __forceinline__ float warp_reduce(float v) {
    #pragma unroll
    for (int o = 16; o; o >>= 1) v += __shfl_xor_sync(0xffffffffu, v, o);
    return v;
}

__device__ __forceinline__ float dot4(float4 a, float4 b) {
    return a.x * b.x + a.y * b.y + a.z * b.z + a.w * b.w;
}

__device__ __forceinline__ void cp_async16(unsigned smem_addr, const void* gptr) {
    asm volatile("cp.async.cg.shared.global [%0], [%1], 16;"
                 :: "r"(smem_addr), "l"(gptr));
}

// Dynamic smem layout (floats):
//  xs    [0,1024)       x / abar / o staging (256 float4)
//  R1    [1024,3072)    512 float4 (phase B)
//  sq    [3072,3328)    256 floats (phase B q chunk)
//  R2    [3328,3584)    64 float4
//  dotp  [3584,3712)    16 warps x 8 slots
//  misc  [3712,3744)    warp accs / zinv / p_k
//  keyS  [3744,8864)    5 keys x 1024 (producers)
//  WvS   [8864,17056)   8 Wv rows (32KB)
//  WoS   [17056,25248)  8 Wo rows (32KB)
#define SM_FLOATS 25248
#define SM_BYTES  (SM_FLOATS * 4)

__global__ void __launch_bounds__(NT, 1)
fused_local_attn(const float* __restrict__ matrix,
                 const float* __restrict__ Wq, const float* __restrict__ bq,
                 const float* __restrict__ Wk,
                 const float* __restrict__ Wv, const float* __restrict__ bv,
                 const float* __restrict__ Wo, const float* __restrict__ bo,
                 const int* __restrict__ ppx, const int* __restrict__ ppy,
                 float* __restrict__ out)
{
    const int tid  = threadIdx.x;
    const int bid  = blockIdx.x;
    const int wid  = tid >> 5;
    const int lane = tid & 31;

    extern __shared__ __align__(16) float sm[];
    float4* xs_4   = (float4*)sm;
    float4* R1_4   = (float4*)(sm + 1024);
    float*  sq     = sm + 3072;
    float4* R2_4   = (float4*)(sm + 3328);
    float*  dotp   = sm + 3584;
    float*  misc   = sm + 3712;
    float4* keyS_4 = (float4*)(sm + 3744);
    float4* WvS_4  = (float4*)(sm + 8864);
    float4* WoS_4  = (float4*)(sm + 17056);

    // ---- Top-of-kernel prefetches ---------------------------------------
    {
        unsigned wv_s = (unsigned)__cvta_generic_to_shared(WvS_4);
        unsigned wo_s = (unsigned)__cvta_generic_to_shared(WoS_4);
        const float4* vsrc = (const float4*)Wv + (size_t)bid * 2048;   // 8 rows
        const float4* osrc = (const float4*)Wo + (size_t)bid * 2048;
        #pragma unroll
        for (int j = 0; j < 4; j++)
            cp_async16(wv_s + (unsigned)(tid + j * 512) * 16u, vsrc + tid + j * 512);
        asm volatile("cp.async.commit_group;");
        #pragma unroll
        for (int j = 0; j < 4; j++)
            cp_async16(wo_s + (unsigned)(tid + j * 512) * 16u, osrc + tid + j * 512);
        asm volatile("cp.async.commit_group;");
    }

    // Biases -> the threads that consume them (tid<8 writes phase tails)
    float my_bq = 0.f, my_bv = 0.f, my_bo = 0.f;
    if (tid < 8) {
        my_bq = __ldcg(&bq[bid * 8 + tid]);
        my_bv = __ldcg(&bv[bid * 8 + tid]);
        my_bo = __ldcg(&bo[bid * 8 + tid]);
    }

    const int px = __ldcg(&ppx[0]), py = __ldcg(&ppy[0]);
    const float* rowbase = matrix + (size_t)(2 * px - WIN) * GW * EMBED;
    const float4* xvec4 = (const float4*)(rowbase + (size_t)(2 * py - WIN) * EMBED);
    const float4* keys4 = (const float4*)(rowbase + (size_t)(py - WIN) * EMBED);

    if (bid < NPROD) {
        unsigned k_s = (unsigned)__cvta_generic_to_shared(keyS_4);
        const float4* ksrc = keys4 + (size_t)(bid * 4) * 256;   // 5 keys = 1280 f4
        #pragma unroll
        for (int j = 0; j < 3; j++) {
            int idx = tid + j * 512;
            if (idx < NKMAX * 256)
                cp_async16(k_s + (unsigned)idx * 16u, ksrc + idx);
        }
        asm volatile("cp.async.commit_group;");
    }

    // =========== Phase A: q = Wq @ x + bq (8 rows/block, 2 warps/row) ====
    {
        if (tid < 256) xs_4[tid] = xvec4[tid];
        __syncthreads();
        int row = bid * 8 + (wid >> 1), half = wid & 1;
        const float4* Wrow = (const float4*)(Wq + (size_t)row * EMBED);
        float acc = dot4(Wrow[half * 128 + 0 * 32 + lane], xs_4[half * 128 + 0 * 32 + lane])
                  + dot4(Wrow[half * 128 + 1 * 32 + lane], xs_4[half * 128 + 1 * 32 + lane])
                  + dot4(Wrow[half * 128 + 2 * 32 + lane], xs_4[half * 128 + 2 * 32 + lane])
                  + dot4(Wrow[half * 128 + 3 * 32 + lane], xs_4[half * 128 + 3 * 32 + lane]);
        acc = warp_reduce(acc);
        if (lane == 0) misc[wid] = acc;
        __syncthreads();
        if (tid < 8) g_q[bid * 8 + tid] = misc[2 * tid] + misc[2 * tid + 1] + my_bq;
    }
    grid_sync();   // #1

    // ===== Phase B: w-partials. fc=bid>>5 (4 f-chunks of 256), et=bid&31 ==
    {
        const int fc = bid >> 5, et = bid & 31;
        const int f0 = fc * 256;
        if (tid < 64) ((float4*)sq)[tid] = __ldcg(&((const float4*)g_q)[f0 / 4 + tid]);
        __syncthreads();
        const int v = tid & 7, fl = tid >> 3;     // fl in [0,64)
        float4 acc = make_float4(0.f, 0.f, 0.f, 0.f);
        #pragma unroll
        for (int i = 0; i < 4; i++) {
            float qf = sq[i * 64 + fl];
            float4 wv = ((const float4*)Wk)[(size_t)(f0 + i * 64 + fl) * 256 + et * 8 + v];
            acc.x += qf * wv.x; acc.y += qf * wv.y; acc.z += qf * wv.z; acc.w += qf * wv.w;
        }
        R1_4[tid] = acc;
        __syncthreads();
        if (tid < 64) {                           // 512 -> 64
            int vv = tid & 7, g = tid >> 3;
            float4 s = make_float4(0.f, 0.f, 0.f, 0.f);
            #pragma unroll
            for (int j = 0; j < 8; j++) {
                float4 t4 = R1_4[vv + 8 * (g * 8 + j)];
                s.x += t4.x; s.y += t4.y; s.z += t4.z; s.w += t4.w;
            }
            R2_4[tid] = s;
        }
        __syncthreads();
        if (tid < 8) {                            // 64 -> 8 float4
            float4 s = make_float4(0.f, 0.f, 0.f, 0.f);
            #pragma unroll
            for (int g = 0; g < 8; g++) {
                float4 t4 = R2_4[tid + 8 * g];
                s.x += t4.x; s.y += t4.y; s.z += t4.z; s.w += t4.w;
            }
            ((float4*)g_wpart[fc])[et * 8 + tid] = s;
        }
    }
    grid_sync();   // #2

    // ===== Phase C (producers): w reduce (4 partials), s_k, p_k, y, z ====
    if (bid < NPROD) {
        asm volatile("cp.async.wait_group 0;");   // keys (and Wv/Wo) resident
        __syncthreads();
        const int nk = (bid == NPROD - 1) ? 5 : 4;
        float4 w4 = make_float4(0.f, 0.f, 0.f, 0.f);
        float4 kv[NKMAX];
        #pragma unroll
        for (int j = 0; j < NKMAX; j++) kv[j] = make_float4(0.f, 0.f, 0.f, 0.f);
        if (tid < 256) {
            w4 = __ldcg(&((const float4*)g_wpart[0])[tid]);
            #pragma unroll
            for (int f = 1; f < 4; f++) {
                float4 t4 = __ldcg(&((const float4*)g_wpart[f])[tid]);
                w4.x += t4.x; w4.y += t4.y; w4.z += t4.z; w4.w += t4.w;
            }
            #pragma unroll
            for (int j = 0; j < NKMAX; j++)
                kv[j] = keyS_4[j * 256 + tid];
        }
        #pragma unroll
        for (int j = 0; j < NKMAX; j++) {
            float p = (j < nk) ? dot4(w4, kv[j]) : 0.f;
            p = warp_reduce(p);
            if (lane == 0) dotp[wid * 8 + j] = p;
        }
        __syncthreads();
        if (tid < NKMAX) {
            float s = 0.f;
            #pragma unroll
            for (int w = 0; w < 8; w++) s += dotp[w * 8 + tid];   // warps 0-7 hold tid<256
            misc[20 + tid] = (tid < nk) ? __expf(s * 0.03125f) : 0.f;
        }
        __syncthreads();
        if (tid < 256) {
            float4 y = make_float4(0.f, 0.f, 0.f, 0.f);
            #pragma unroll
            for (int j = 0; j < NKMAX; j++) {
                float pk = misc[20 + j];
                y.x += pk * kv[j].x; y.y += pk * kv[j].y;
                y.z += pk * kv[j].z; y.w += pk * kv[j].w;
            }
            ((float4*)g_ypart[bid])[tid] = y;
        }
        if (tid == 0) {
            float z = 0.f;
            #pragma unroll
            for (int j = 0; j < NKMAX; j++) z += misc[20 + j];
            g_zpart[bid] = z;
        }
    }
    grid_sync();   // #3

    // ===== Phase E: abar from y/z parts, o = Wv @ abar + bv (smem Wv) ====
    asm volatile("cp.async.wait_group 0;");
    __syncthreads();
    {
        if (wid == 0) {
            float z = __ldcg(&g_zpart[lane]);     // 32 values
            z = warp_reduce(z);
            if (lane == 0) misc[16] = 1.f / z;
        }
        float4 s0 = make_float4(0.f, 0.f, 0.f, 0.f);
        float4 s1 = make_float4(0.f, 0.f, 0.f, 0.f);
        if (tid < 256) {
            #pragma unroll
            for (int p = 0; p < NPROD; p += 2) {
                float4 a0 = __ldcg(&((const float4*)g_ypart[p])[tid]);
                float4 a1 = __ldcg(&((const float4*)g_ypart[p + 1])[tid]);
                s0.x += a0.x; s0.y += a0.y; s0.z += a0.z; s0.w += a0.w;
                s1.x += a1.x; s1.y += a1.y; s1.z += a1.z; s1.w += a1.w;
            }
        }
        __syncthreads();                           // zinv ready
        if (tid < 256) {
            float zinv = misc[16];
            float4 ab;
            ab.x = (s0.x + s1.x) * zinv; ab.y = (s0.y + s1.y) * zinv;
            ab.z = (s0.z + s1.z) * zinv; ab.w = (s0.w + s1.w) * zinv;
            xs_4[tid] = ab;
        }
        __syncthreads();
        int r = wid >> 1, half = wid & 1;
        float acc = dot4(WvS_4[r * 256 + half * 128 + 0 * 32 + lane], xs_4[half * 128 + 0 * 32 + lane])
                  + dot4(WvS_4[r * 256 + half * 128 + 1 * 32 + lane], xs_4[half * 128 + 1 * 32 + lane])
                  + dot4(WvS_4[r * 256 + half * 128 + 2 * 32 + lane], xs_4[half * 128 + 2 * 32 + lane])
                  + dot4(WvS_4[r * 256 + half * 128 + 3 * 32 + lane], xs_4[half * 128 + 3 * 32 + lane]);
        acc = warp_reduce(acc);
        if (lane == 0) misc[wid] = acc;
        __syncthreads();
        if (tid < 8) g_o[bid * 8 + tid] = misc[2 * tid] + misc[2 * tid + 1] + my_bv;
    }
    grid_sync();   // #4

    // ===== Phase F: out = Wo @ o + bo (smem Wo) ==========================
    {
        if (tid < 256) xs_4[tid] = __ldcg(&((const float4*)g_o)[tid]);
        __syncthreads();
        int r = wid >> 1, half = wid & 1;
        float acc = dot4(WoS_4[r * 256 + half * 128 + 0 * 32 + lane], xs_4[half * 128 + 0 * 32 + lane])
                  + dot4(WoS_4[r * 256 + half * 128 + 1 * 32 + lane], xs_4[half * 128 + 1 * 32 + lane])
                  + dot4(WoS_4[r * 256 + half * 128 + 2 * 32 + lane], xs_4[half * 128 + 2 * 32 + lane])
                  + dot4(WoS_4[r * 256 + half * 128 + 3 * 32 + lane], xs_4[half * 128 + 3 * 32 + lane]);
        acc = warp_reduce(acc);
        if (lane == 0) misc[wid] = acc;
        __syncthreads();
        if (tid < 8) out[bid * 8 + tid] = misc[2 * tid] + misc[2 * tid + 1] + my_bo;
    }
}

extern "C" void kernel_launch(void* const* d_in, const int* in_sizes, int n_in,
                              void* d_out, int out_size) {
    const float* matrix = (const float*)d_in[0];
    const float* Wq = (const float*)d_in[1];
    const float* bq = (const float*)d_in[2];
    const float* Wk = (const float*)d_in[3];
    // d_in[4] = bk: eliminated (cancels in softmax ratio)
    const float* Wv = (const float*)d_in[5];
    const float* bv = (const float*)d_in[6];
    const float* Wo = (const float*)d_in[7];
    const float* bo = (const float*)d_in[8];
    const int* px = (const int*)d_in[9];
    const int* py = (const int*)d_in[10];

    cudaFuncSetAttribute(fused_local_attn,
                         cudaFuncAttributeMaxDynamicSharedMemorySize, SM_BYTES);
    fused_local_attn<<<NB, NT, SM_BYTES>>>(matrix, Wq, bq, Wk, Wv, bv, Wo, bo,
                                           px, py, (float*)d_out);
}